// round 1
// baseline (speedup 1.0000x reference)
#include <cuda_runtime.h>
#include <cstdint>

// Problem constants (from reference): N=50000, E=800000, IN_DIM=128, H=8, D=16
#define NMAX   50000
#define EMAX   800000
#define SCAN_B 1024

// ---- scratch (__device__ globals; no allocation allowed) ----
__device__ float g_z[(size_t)NMAX * 128];     // projected features z[n][c], c = h*16+d
__device__ float g_Wt[128 * 128];             // W reshuffled to [k][c]
__device__ int   g_cnt[NMAX];                 // degree counts, later scatter cursor
__device__ int   g_off[NMAX + 1];             // CSR offsets (exclusive scan)
__device__ int   g_srcs[EMAX];                // src ids sorted by dst
__device__ int   g_bsum[64];                  // scan block partials

// ---------------------------------------------------------------------------
__global__ void k_zero(int n) {
    int i = blockIdx.x * blockDim.x + threadIdx.x;
    if (i < n) g_cnt[i] = 0;
}

// Wfc is [H=8][IN=128][D=16]; build Wt[k][c] with c = h*16+d so per-k rows are
// contiguous 512B (coalesced float4 loads in the GEMM).
__global__ void k_wt(const float* __restrict__ Wfc) {
    int i = blockIdx.x * blockDim.x + threadIdx.x;
    if (i < 128 * 128) {
        int k = i >> 7, c = i & 127;
        g_Wt[i] = Wfc[(c >> 4) * 2048 + k * 16 + (c & 15)];
    }
}

// z = h @ Wt.  Block = 256 thr = 8 warps; block covers 32 rows; each warp does
// 4 rows x 128 cols; lane owns 4 consecutive cols (one float4 of Wt per k).
__global__ __launch_bounds__(256) void k_gemm(const float* __restrict__ h, int N) {
    __shared__ float sh[32 * 128];
    int base = blockIdx.x * 32;

    const float4* h4 = (const float4*)h;
    float4* sh4 = (float4*)sh;
    for (int idx = threadIdx.x; idx < 32 * 32; idx += 256) {
        int r = idx >> 5;
        float4 v = make_float4(0.f, 0.f, 0.f, 0.f);
        if (base + r < N) v = h4[(size_t)(base + r) * 32 + (idx & 31)];
        sh4[idx] = v;
    }
    __syncthreads();

    int warp = threadIdx.x >> 5, lane = threadIdx.x & 31;
    const float* hr = sh + warp * 4 * 128;
    const float4* Wt4 = (const float4*)g_Wt;

    float4 a0 = make_float4(0.f,0.f,0.f,0.f), a1 = a0, a2 = a0, a3 = a0;
#pragma unroll 4
    for (int k = 0; k < 128; k++) {
        float4 w = Wt4[k * 32 + lane];
        float b0 = hr[k], b1 = hr[128 + k], b2 = hr[256 + k], b3 = hr[384 + k];
        a0.x += w.x * b0; a0.y += w.y * b0; a0.z += w.z * b0; a0.w += w.w * b0;
        a1.x += w.x * b1; a1.y += w.y * b1; a1.z += w.z * b1; a1.w += w.w * b1;
        a2.x += w.x * b2; a2.y += w.y * b2; a2.z += w.z * b2; a2.w += w.w * b2;
        a3.x += w.x * b3; a3.y += w.y * b3; a3.z += w.z * b3; a3.w += w.w * b3;
    }
    float4* z4 = (float4*)g_z;
    int r = base + warp * 4;
    if (r + 0 < N) z4[(size_t)(r + 0) * 32 + lane] = a0;
    if (r + 1 < N) z4[(size_t)(r + 1) * 32 + lane] = a1;
    if (r + 2 < N) z4[(size_t)(r + 2) * 32 + lane] = a2;
    if (r + 3 < N) z4[(size_t)(r + 3) * 32 + lane] = a3;
}

// ---------------------------------------------------------------------------
__global__ void k_hist(const int* __restrict__ dst, int E) {
    int i = blockIdx.x * blockDim.x + threadIdx.x;
    if (i < E) atomicAdd(&g_cnt[dst[i]], 1);
}

// 3-phase exclusive scan of g_cnt -> g_off
__global__ __launch_bounds__(SCAN_B) void k_scanA(int N) {
    __shared__ int wsum[32];
    int i = blockIdx.x * SCAN_B + threadIdx.x;
    int lane = threadIdx.x & 31, wid = threadIdx.x >> 5;
    int x = (i < N) ? g_cnt[i] : 0;
#pragma unroll
    for (int d = 1; d < 32; d <<= 1) {
        int y = __shfl_up_sync(0xFFFFFFFFu, x, d);
        if (lane >= d) x += y;
    }
    if (lane == 31) wsum[wid] = x;
    __syncthreads();
    if (wid == 0) {
        int s = wsum[lane];
#pragma unroll
        for (int d = 1; d < 32; d <<= 1) {
            int y = __shfl_up_sync(0xFFFFFFFFu, s, d);
            if (lane >= d) s += y;
        }
        wsum[lane] = s;
    }
    __syncthreads();
    int incl = x + (wid ? wsum[wid - 1] : 0);
    if (i < N) g_off[i] = incl;                       // inclusive (block-local)
    if (threadIdx.x == SCAN_B - 1) g_bsum[blockIdx.x] = incl;  // block total
}

__global__ void k_scanB(int nb) {
    if (threadIdx.x == 0 && blockIdx.x == 0) {
        int acc = 0;
        for (int b = 0; b < nb; b++) { int t = g_bsum[b]; g_bsum[b] = acc; acc += t; }
    }
}

__global__ __launch_bounds__(SCAN_B) void k_scanC(int N, int E) {
    int i = blockIdx.x * SCAN_B + threadIdx.x;
    if (i < N) {
        int excl = g_off[i] - g_cnt[i] + g_bsum[blockIdx.x];
        g_off[i] = excl;
        g_cnt[i] = excl;      // cursor for scatter
    }
    if (i == 0) g_off[N] = E;
}

__global__ void k_scatter(const int* __restrict__ src, const int* __restrict__ dst, int E) {
    int i = blockIdx.x * blockDim.x + threadIdx.x;
    if (i < E) {
        int p = atomicAdd(&g_cnt[dst[i]], 1);
        g_srcs[p] = src[i];
    }
}

// ---------------------------------------------------------------------------
// One warp per dst node. Lane owns 4 channels (float4).  Softmax without the
// max-shift (shift-invariant; scores bounded ~|25| so exp stays finite).
__global__ __launch_bounds__(256) void k_agg(const float* __restrict__ h,
                                             const float* __restrict__ snorm,
                                             float* __restrict__ out, int N) {
    int gw = (blockIdx.x * 256 + threadIdx.x) >> 5;
    int lane = threadIdx.x & 31;
    if (gw >= N) return;

    const float4* z4 = (const float4*)g_z;
    float4 zd = z4[(size_t)gw * 32 + lane];
    int beg = g_off[gw], end = g_off[gw + 1];

    float4 se = make_float4(0.f,0.f,0.f,0.f);
    float4 sz = se;
    for (int e = beg; e < end; e++) {
        int s = g_srcs[e];
        float4 zs = z4[(size_t)s * 32 + lane];
        float t;
        t = __expf(zs.x * zd.x); se.x += t; sz.x += t * zs.x;
        t = __expf(zs.y * zd.y); se.y += t; sz.y += t * zs.y;
        t = __expf(zs.z * zd.z); se.z += t; sz.z += t * zs.z;
        t = __expf(zs.w * zd.w); se.w += t; sz.w += t * zs.w;
    }

    float sn = snorm[gw];
    float4 hv = ((const float4*)h)[(size_t)gw * 32 + lane];
    bool has = (end > beg);
    float4 o;
#define ELU_CH(c) { float a = has ? (sz.c / se.c) : 0.f; a *= sn; \
                    o.c = hv.c + (a > 0.f ? a : expm1f(a)); }
    ELU_CH(x) ELU_CH(y) ELU_CH(z) ELU_CH(w)
#undef ELU_CH
    ((float4*)out)[(size_t)gw * 32 + lane] = o;
}

// ---------------------------------------------------------------------------
extern "C" void kernel_launch(void* const* d_in, const int* in_sizes, int n_in,
                              void* d_out, int out_size) {
    const float* h     = (const float*)d_in[0];   // [N,128]
    const float* snorm = (const float*)d_in[1];   // [N,1]
    const float* Wfc   = (const float*)d_in[2];   // [8,128,16]
    const int*   src   = (const int*)d_in[3];     // [E]
    const int*   dst   = (const int*)d_in[4];     // [E]
    float*       out   = (float*)d_out;           // [N,128]

    int N = in_sizes[1];
    int E = in_sizes[3];

    k_zero<<<(N + 255) / 256, 256>>>(N);
    k_wt<<<64, 256>>>(Wfc);
    k_gemm<<<(N + 31) / 32, 256>>>(h, N);
    k_hist<<<(E + 255) / 256, 256>>>(dst, E);

    int nb = (N + SCAN_B - 1) / SCAN_B;
    k_scanA<<<nb, SCAN_B>>>(N);
    k_scanB<<<1, 32>>>(nb);
    k_scanC<<<nb, SCAN_B>>>(N, E);

    k_scatter<<<(E + 255) / 256, 256>>>(src, dst, E);
    k_agg<<<(N + 7) / 8, 256>>>(h, snorm, out, N);
}

// round 2
// speedup vs baseline: 1.0307x; 1.0307x over previous
#include <cuda_runtime.h>
#include <cstdint>

// Problem constants: N=50000, E=800000, IN_DIM=128, H=8, D=16
#define NMAX   50000
#define EMAX   800000
#define SCAN_B 1024

// ---- scratch (__device__ globals; no allocation allowed) ----
__device__ float g_z[(size_t)NMAX * 128];     // projected features z[n][c], c = h*16+d
__device__ float g_Wt[128 * 128];             // W reshuffled to [k][c]
__device__ int   g_cnt[NMAX];                 // degree counts, later scatter cursor
__device__ int   g_off[NMAX + 1];             // CSR offsets (exclusive scan)
__device__ int   g_srcs[EMAX];                // src ids grouped by dst
__device__ int   g_bsum[64];                  // scan block totals (raw)

// ---------------------------------------------------------------------------
// Prep: zero the degree counters AND build Wt[k][c] (c = h*16+d) in one kernel.
__global__ void k_prep(const float* __restrict__ Wfc, int N) {
    int i = blockIdx.x * blockDim.x + threadIdx.x;
    if (i < N) g_cnt[i] = 0;
    if (i < 128 * 128) {
        int k = i >> 7, c = i & 127;
        g_Wt[i] = Wfc[(c >> 4) * 2048 + k * 16 + (c & 15)];
    }
}

// ---------------------------------------------------------------------------
// GEMM z = h @ Wt, with the dst-histogram fused at the top (fire-and-forget
// REDs drain under the FMA-bound mainloop).
// Block = 256 thr = 8 warps covering 32 rows; warp does 4 rows x 128 cols.
__global__ __launch_bounds__(256) void k_gemm_hist(const float* __restrict__ h,
                                                   const int* __restrict__ dst,
                                                   int N, int E) {
    // --- fused histogram: grid-stride over edges ---
    {
        int stride = gridDim.x * 256;
        for (int i = blockIdx.x * 256 + threadIdx.x; i < E; i += stride)
            atomicAdd(&g_cnt[dst[i]], 1);
    }

    __shared__ float sh[32 * 128];
    int base = blockIdx.x * 32;

    const float4* h4 = (const float4*)h;
    float4* sh4 = (float4*)sh;
    for (int idx = threadIdx.x; idx < 32 * 32; idx += 256) {
        int r = idx >> 5;
        float4 v = make_float4(0.f, 0.f, 0.f, 0.f);
        if (base + r < N) v = h4[(size_t)(base + r) * 32 + (idx & 31)];
        sh4[idx] = v;
    }
    __syncthreads();

    int warp = threadIdx.x >> 5, lane = threadIdx.x & 31;
    const float* hr = sh + warp * 4 * 128;
    const float4* Wt4 = (const float4*)g_Wt;

    float4 a0 = make_float4(0.f,0.f,0.f,0.f), a1 = a0, a2 = a0, a3 = a0;
#pragma unroll 4
    for (int k = 0; k < 128; k++) {
        float4 w = Wt4[k * 32 + lane];
        float b0 = hr[k], b1 = hr[128 + k], b2 = hr[256 + k], b3 = hr[384 + k];
        a0.x += w.x * b0; a0.y += w.y * b0; a0.z += w.z * b0; a0.w += w.w * b0;
        a1.x += w.x * b1; a1.y += w.y * b1; a1.z += w.z * b1; a1.w += w.w * b1;
        a2.x += w.x * b2; a2.y += w.y * b2; a2.z += w.z * b2; a2.w += w.w * b2;
        a3.x += w.x * b3; a3.y += w.y * b3; a3.z += w.z * b3; a3.w += w.w * b3;
    }
    float4* z4 = (float4*)g_z;
    int r = base + warp * 4;
    if (r + 0 < N) z4[(size_t)(r + 0) * 32 + lane] = a0;
    if (r + 1 < N) z4[(size_t)(r + 1) * 32 + lane] = a1;
    if (r + 2 < N) z4[(size_t)(r + 2) * 32 + lane] = a2;
    if (r + 3 < N) z4[(size_t)(r + 3) * 32 + lane] = a3;
}

// ---------------------------------------------------------------------------
// Scan phase A: block-local inclusive scan of g_cnt into g_off, block totals
// into g_bsum.
__global__ __launch_bounds__(SCAN_B) void k_scanA(int N) {
    __shared__ int wsum[32];
    int i = blockIdx.x * SCAN_B + threadIdx.x;
    int lane = threadIdx.x & 31, wid = threadIdx.x >> 5;
    int x = (i < N) ? g_cnt[i] : 0;
#pragma unroll
    for (int d = 1; d < 32; d <<= 1) {
        int y = __shfl_up_sync(0xFFFFFFFFu, x, d);
        if (lane >= d) x += y;
    }
    if (lane == 31) wsum[wid] = x;
    __syncthreads();
    if (wid == 0) {
        int s = wsum[lane];
#pragma unroll
        for (int d = 1; d < 32; d <<= 1) {
            int y = __shfl_up_sync(0xFFFFFFFFu, s, d);
            if (lane >= d) s += y;
        }
        wsum[lane] = s;
    }
    __syncthreads();
    int incl = x + (wid ? wsum[wid - 1] : 0);
    if (i < N) g_off[i] = incl;
    if (threadIdx.x == SCAN_B - 1) g_bsum[blockIdx.x] = incl;
}

// Scan phase C with the (tiny, <=64-entry) block-prefix reduction inlined:
// every block redundantly sums g_bsum[0..bid-1] itself — ~60 cycles, kills the
// separate 1-thread scanB launch.
__global__ __launch_bounds__(SCAN_B) void k_scanC(int N, int E) {
    __shared__ int sprefix;
    {
        int t = threadIdx.x;
        int v = (t < 64 && t < (int)blockIdx.x) ? g_bsum[t] : 0;
        if (t < 64) {
#pragma unroll
            for (int d = 16; d > 0; d >>= 1) v += __shfl_down_sync(0xFFFFFFFFu, v, d);
            if (t == 0) sprefix = v;
            if (t == 32) atomicAdd(&sprefix, v);   // second warp's partial
        }
        if (t == 0 && blockIdx.x == 0) sprefix = 0;
    }
    __syncthreads();
    int prefix = sprefix;

    int i = blockIdx.x * SCAN_B + threadIdx.x;
    if (i < N) {
        int excl = g_off[i] - g_cnt[i] + prefix;
        g_off[i] = excl;
        g_cnt[i] = excl;      // cursor for scatter
    }
    if (i == 0) g_off[N] = E;
}

__global__ void k_scatter(const int* __restrict__ src, const int* __restrict__ dst, int E) {
    int i = blockIdx.x * blockDim.x + threadIdx.x;
    if (i < E) {
        int p = atomicAdd(&g_cnt[dst[i]], 1);
        g_srcs[p] = src[i];
    }
}

// ---------------------------------------------------------------------------
// One warp per dst node; lane owns 4 channels. Softmax without max-shift
// (shift-invariant; |score| <= ~30 so exp stays finite in fp32).
// Edge loop unrolled x4 so 4 row-gathers are in flight per warp.
__global__ __launch_bounds__(256) void k_agg(const float* __restrict__ h,
                                             const float* __restrict__ snorm,
                                             float* __restrict__ out, int N) {
    int gw = (blockIdx.x * 256 + threadIdx.x) >> 5;
    int lane = threadIdx.x & 31;
    if (gw >= N) return;

    const float4* z4 = (const float4*)g_z;
    float4 zd = z4[(size_t)gw * 32 + lane];
    int beg = g_off[gw], end = g_off[gw + 1];

    float4 se = make_float4(0.f,0.f,0.f,0.f);
    float4 sz = se;

#define ACC(zs) { float t; \
    t = __expf((zs).x * zd.x); se.x += t; sz.x += t * (zs).x; \
    t = __expf((zs).y * zd.y); se.y += t; sz.y += t * (zs).y; \
    t = __expf((zs).z * zd.z); se.z += t; sz.z += t * (zs).z; \
    t = __expf((zs).w * zd.w); se.w += t; sz.w += t * (zs).w; }

    int e = beg;
    for (; e + 3 < end; e += 4) {
        int s0 = g_srcs[e + 0], s1 = g_srcs[e + 1];
        int s2 = g_srcs[e + 2], s3 = g_srcs[e + 3];
        float4 q0 = z4[(size_t)s0 * 32 + lane];
        float4 q1 = z4[(size_t)s1 * 32 + lane];
        float4 q2 = z4[(size_t)s2 * 32 + lane];
        float4 q3 = z4[(size_t)s3 * 32 + lane];
        ACC(q0) ACC(q1) ACC(q2) ACC(q3)
    }
    for (; e < end; e++) {
        float4 q = z4[(size_t)g_srcs[e] * 32 + lane];
        ACC(q)
    }
#undef ACC

    float sn = snorm[gw];
    float4 hv = ((const float4*)h)[(size_t)gw * 32 + lane];
    bool has = (end > beg);
    float4 o;
#define ELU_CH(c) { float a = has ? (sz.c / se.c) : 0.f; a *= sn; \
                    o.c = hv.c + (a > 0.f ? a : expm1f(a)); }
    ELU_CH(x) ELU_CH(y) ELU_CH(z) ELU_CH(w)
#undef ELU_CH
    ((float4*)out)[(size_t)gw * 32 + lane] = o;
}

// ---------------------------------------------------------------------------
extern "C" void kernel_launch(void* const* d_in, const int* in_sizes, int n_in,
                              void* d_out, int out_size) {
    const float* h     = (const float*)d_in[0];   // [N,128]
    const float* snorm = (const float*)d_in[1];   // [N,1]
    const float* Wfc   = (const float*)d_in[2];   // [8,128,16]
    const int*   src   = (const int*)d_in[3];     // [E]
    const int*   dst   = (const int*)d_in[4];     // [E]
    float*       out   = (float*)d_out;           // [N,128]

    int N = in_sizes[1];
    int E = in_sizes[3];

    k_prep<<<(N + 255) / 256, 256>>>(Wfc, N);
    k_gemm_hist<<<(N + 31) / 32, 256>>>(h, dst, N, E);

    int nb = (N + SCAN_B - 1) / SCAN_B;
    k_scanA<<<nb, SCAN_B>>>(N);
    k_scanC<<<nb, SCAN_B>>>(N, E);

    k_scatter<<<(E + 255) / 256, 256>>>(src, dst, E);
    k_agg<<<(N + 7) / 8, 256>>>(h, snorm, out, N);
}

// round 3
// speedup vs baseline: 1.0540x; 1.0226x over previous
#include <cuda_runtime.h>
#include <cstdint>

// Problem constants: N=50000, E=800000, IN_DIM=128, H=8, D=16
#define NMAX   50000
#define EMAX   800000
#define SCAN_B 1024

// ---- scratch (__device__ globals; no allocation allowed) ----
__device__ float g_z[(size_t)NMAX * 128];     // projected features z[n][c], c = h*16+d
__device__ float g_Wt[128 * 128];             // W reshuffled to [k][c]
__device__ int   g_cnt[NMAX];                 // degree counts, later scatter cursor
__device__ int   g_off[NMAX + 1];             // CSR offsets (exclusive scan)
__device__ int   g_srcs[EMAX];                // src ids grouped by dst
__device__ int   g_bsum[64];                  // scan block totals (raw)

// ---------------------------------------------------------------------------
__global__ void k_zero(int N) {
    int i = blockIdx.x * blockDim.x + threadIdx.x;
    if (i < N) g_cnt[i] = 0;
}

// Wfc is [H=8][IN=128][D=16]; build Wt[k][c] with c = h*16+d.
__global__ void k_wt(const float* __restrict__ Wfc) {
    int i = blockIdx.x * blockDim.x + threadIdx.x;
    if (i < 128 * 128) {
        int k = i >> 7, c = i & 127;
        g_Wt[i] = Wfc[(c >> 4) * 2048 + k * 16 + (c & 15)];
    }
}

// ---------------------------------------------------------------------------
// Pure GEMM z = h @ Wt (histogram un-fused; it runs concurrently on the CSR
// stream). Block = 256 thr = 8 warps covering 32 rows; warp does 4 rows.
__global__ __launch_bounds__(256) void k_gemm(const float* __restrict__ h, int N) {
    __shared__ float sh[32 * 128];
    int base = blockIdx.x * 32;

    const float4* h4 = (const float4*)h;
    float4* sh4 = (float4*)sh;
    for (int idx = threadIdx.x; idx < 32 * 32; idx += 256) {
        int r = idx >> 5;
        float4 v = make_float4(0.f, 0.f, 0.f, 0.f);
        if (base + r < N) v = h4[(size_t)(base + r) * 32 + (idx & 31)];
        sh4[idx] = v;
    }
    __syncthreads();

    int warp = threadIdx.x >> 5, lane = threadIdx.x & 31;
    const float* hr = sh + warp * 4 * 128;
    const float4* Wt4 = (const float4*)g_Wt;

    float4 a0 = make_float4(0.f,0.f,0.f,0.f), a1 = a0, a2 = a0, a3 = a0;
#pragma unroll 4
    for (int k = 0; k < 128; k++) {
        float4 w = Wt4[k * 32 + lane];
        float b0 = hr[k], b1 = hr[128 + k], b2 = hr[256 + k], b3 = hr[384 + k];
        a0.x += w.x * b0; a0.y += w.y * b0; a0.z += w.z * b0; a0.w += w.w * b0;
        a1.x += w.x * b1; a1.y += w.y * b1; a1.z += w.z * b1; a1.w += w.w * b1;
        a2.x += w.x * b2; a2.y += w.y * b2; a2.z += w.z * b2; a2.w += w.w * b2;
        a3.x += w.x * b3; a3.y += w.y * b3; a3.z += w.z * b3; a3.w += w.w * b3;
    }
    float4* z4 = (float4*)g_z;
    int r = base + warp * 4;
    if (r + 0 < N) z4[(size_t)(r + 0) * 32 + lane] = a0;
    if (r + 1 < N) z4[(size_t)(r + 1) * 32 + lane] = a1;
    if (r + 2 < N) z4[(size_t)(r + 2) * 32 + lane] = a2;
    if (r + 3 < N) z4[(size_t)(r + 3) * 32 + lane] = a3;
}

// ---------------------------------------------------------------------------
__global__ void k_hist(const int* __restrict__ dst, int E) {
    int i = blockIdx.x * blockDim.x + threadIdx.x;
    if (i < E) atomicAdd(&g_cnt[dst[i]], 1);
}

// Scan A: block-local inclusive scan of g_cnt into g_off, totals into g_bsum.
__global__ __launch_bounds__(SCAN_B) void k_scanA(int N) {
    __shared__ int wsum[32];
    int i = blockIdx.x * SCAN_B + threadIdx.x;
    int lane = threadIdx.x & 31, wid = threadIdx.x >> 5;
    int x = (i < N) ? g_cnt[i] : 0;
#pragma unroll
    for (int d = 1; d < 32; d <<= 1) {
        int y = __shfl_up_sync(0xFFFFFFFFu, x, d);
        if (lane >= d) x += y;
    }
    if (lane == 31) wsum[wid] = x;
    __syncthreads();
    if (wid == 0) {
        int s = wsum[lane];
#pragma unroll
        for (int d = 1; d < 32; d <<= 1) {
            int y = __shfl_up_sync(0xFFFFFFFFu, s, d);
            if (lane >= d) s += y;
        }
        wsum[lane] = s;
    }
    __syncthreads();
    int incl = x + (wid ? wsum[wid - 1] : 0);
    if (i < N) g_off[i] = incl;
    if (threadIdx.x == SCAN_B - 1) g_bsum[blockIdx.x] = incl;
}

// Scan C: per-block prefix over <=64 block totals inlined, then finalize
// exclusive offsets and initialize the scatter cursors.
__global__ __launch_bounds__(SCAN_B) void k_scanC(int N, int E) {
    __shared__ int sprefix;
    {
        int t = threadIdx.x;
        if (t == 0) sprefix = 0;
        __syncthreads();
        int v = (t < 64 && t < (int)blockIdx.x) ? g_bsum[t] : 0;
        if (t < 64) {
#pragma unroll
            for (int d = 16; d > 0; d >>= 1) v += __shfl_down_sync(0xFFFFFFFFu, v, d);
            if ((t & 31) == 0 && v) atomicAdd(&sprefix, v);
        }
    }
    __syncthreads();
    int prefix = sprefix;

    int i = blockIdx.x * SCAN_B + threadIdx.x;
    if (i < N) {
        int excl = g_off[i] - g_cnt[i] + prefix;
        g_off[i] = excl;
        g_cnt[i] = excl;      // cursor for scatter
    }
    if (i == 0) g_off[N] = E;
}

__global__ void k_scatter(const int* __restrict__ src, const int* __restrict__ dst, int E) {
    int i = blockIdx.x * blockDim.x + threadIdx.x;
    if (i < E) {
        int p = atomicAdd(&g_cnt[dst[i]], 1);
        g_srcs[p] = src[i];
    }
}

// ---------------------------------------------------------------------------
// One warp per dst node; lane owns 4 channels. Softmax without max-shift
// (shift-invariant; |score| small enough that exp stays finite in fp32).
__global__ __launch_bounds__(256) void k_agg(const float* __restrict__ h,
                                             const float* __restrict__ snorm,
                                             float* __restrict__ out, int N) {
    int gw = (blockIdx.x * 256 + threadIdx.x) >> 5;
    int lane = threadIdx.x & 31;
    if (gw >= N) return;

    const float4* z4 = (const float4*)g_z;
    float4 zd = z4[(size_t)gw * 32 + lane];
    int beg = g_off[gw], end = g_off[gw + 1];

    float4 se = make_float4(0.f,0.f,0.f,0.f);
    float4 sz = se;

#define ACC(zs) { float t; \
    t = __expf((zs).x * zd.x); se.x += t; sz.x += t * (zs).x; \
    t = __expf((zs).y * zd.y); se.y += t; sz.y += t * (zs).y; \
    t = __expf((zs).z * zd.z); se.z += t; sz.z += t * (zs).z; \
    t = __expf((zs).w * zd.w); se.w += t; sz.w += t * (zs).w; }

    int e = beg;
    for (; e + 3 < end; e += 4) {
        int s0 = g_srcs[e + 0], s1 = g_srcs[e + 1];
        int s2 = g_srcs[e + 2], s3 = g_srcs[e + 3];
        float4 q0 = z4[(size_t)s0 * 32 + lane];
        float4 q1 = z4[(size_t)s1 * 32 + lane];
        float4 q2 = z4[(size_t)s2 * 32 + lane];
        float4 q3 = z4[(size_t)s3 * 32 + lane];
        ACC(q0) ACC(q1) ACC(q2) ACC(q3)
    }
    for (; e < end; e++) {
        float4 q = z4[(size_t)g_srcs[e] * 32 + lane];
        ACC(q)
    }
#undef ACC

    float sn = snorm[gw];
    float4 hv = ((const float4*)h)[(size_t)gw * 32 + lane];
    bool has = (end > beg);
    float4 o;
#define ELU_CH(c) { float a = has ? (sz.c / se.c) : 0.f; a *= sn; \
                    o.c = hv.c + (a > 0.f ? a : expm1f(a)); }
    ELU_CH(x) ELU_CH(y) ELU_CH(z) ELU_CH(w)
#undef ELU_CH
    ((float4*)out)[(size_t)gw * 32 + lane] = o;
}

// ---------------------------------------------------------------------------
extern "C" void kernel_launch(void* const* d_in, const int* in_sizes, int n_in,
                              void* d_out, int out_size) {
    const float* h     = (const float*)d_in[0];   // [N,128]
    const float* snorm = (const float*)d_in[1];   // [N,1]
    const float* Wfc   = (const float*)d_in[2];   // [8,128,16]
    const int*   src   = (const int*)d_in[3];     // [E]
    const int*   dst   = (const int*)d_in[4];     // [E]
    float*       out   = (float*)d_out;           // [N,128]

    int N = in_sizes[1];
    int E = in_sizes[3];

    // Lazily-created side stream + events (host resources only; created on the
    // first (correctness) call, long before graph capture begins).
    static cudaStream_t s2 = nullptr;
    static cudaEvent_t evFork = nullptr, evJoin = nullptr;
    if (!s2) {
        cudaStreamCreateWithFlags(&s2, cudaStreamNonBlocking);
        cudaEventCreateWithFlags(&evFork, cudaEventDisableTiming);
        cudaEventCreateWithFlags(&evJoin, cudaEventDisableTiming);
    }

    int nb = (N + SCAN_B - 1) / SCAN_B;

    // Fork: CSR build chain on s2, GEMM chain on the main (default) stream.
    cudaEventRecord(evFork, 0);
    cudaStreamWaitEvent(s2, evFork, 0);

    // --- branch B (s2): CSR build ---
    k_zero   <<<(N + 255) / 256, 256, 0, s2>>>(N);
    k_hist   <<<(E + 255) / 256, 256, 0, s2>>>(dst, E);
    k_scanA  <<<nb, SCAN_B, 0, s2>>>(N);
    k_scanC  <<<nb, SCAN_B, 0, s2>>>(N, E);
    k_scatter<<<(E + 255) / 256, 256, 0, s2>>>(src, dst, E);
    cudaEventRecord(evJoin, s2);

    // --- branch A (default stream): projection ---
    k_wt  <<<64, 256>>>(Wfc);
    k_gemm<<<(N + 31) / 32, 256>>>(h, N);

    // Join, then aggregate + epilogue.
    cudaStreamWaitEvent(0, evJoin, 0);
    k_agg<<<(N + 7) / 8, 256>>>(h, snorm, out, N);
}